// round 11
// baseline (speedup 1.0000x reference)
#include <cuda_runtime.h>
#include <math.h>

#define MAXN 100000
#define MAXE 1200000
#define SCAN_B 512
#define MAXBLK 256

typedef unsigned long long ull;

// packed fp32x2 FMA (Blackwell): d = a*b + c elementwise on reg pairs
#define FMA2(d, a, b, c) \
    asm("fma.rn.f32x2 %0, %1, %2, %3;" : "=l"(d) : "l"(a), "l"(b), "l"(c))
#define PK2(d, lo, hi) \
    asm("mov.b64 %0, {%1, %2};" : "=l"(d) : "f"(lo), "f"(hi))
#define UPK2(lo, hi, s) \
    asm("mov.b64 {%0, %1}, %2;" : "=f"(lo), "=f"(hi) : "l"(s))

// ---- scratch (static __device__, allocation-free; zero-initialized at load) ----
__device__ __align__(16) float g_h[(size_t)MAXN * 64];   // h = x@W (row stride = Do)
__device__ float               g_as[MAXN];               // h @ a_src
__device__ float               g_ad[MAXN];               // h @ a_dst
__device__ __align__(16) float g_x[(size_t)MAXN * 64];   // layer output -> next input
__device__ int                 g_deg[MAXN];              // in-degree (ZERO at call entry)
__device__ int                 g_rowptr[MAXN];           // after scatter: rowptr[n] = end(n)
__device__ int                 g_csrc[MAXE];             // CSR src indices (grouped by dst)
// decoupled-lookback scan state (ZERO flags at call entry)
__device__ volatile int        g_flag[MAXBLK];
__device__ volatile int        g_aggr[MAXBLK];
__device__ volatile int        g_incl[MAXBLK];

__device__ __forceinline__ float lrelu(float x) { return x > 0.f ? x : 0.2f * x; }

// ================= CSR build: 3 kernels =================

__global__ void hist_k(const int* __restrict__ ei, int E) {
    int i4 = blockIdx.x * blockDim.x + threadIdx.x;
    const int* dst = ei + E;
    int base = i4 * 4;
    if (base + 3 < E) {
        int4 d = *(const int4*)(dst + base);
        atomicAdd(&g_deg[d.x], 1);
        atomicAdd(&g_deg[d.y], 1);
        atomicAdd(&g_deg[d.z], 1);
        atomicAdd(&g_deg[d.w], 1);
    } else {
        for (int i = base; i < E; i++) atomicAdd(&g_deg[dst[i]], 1);
    }
}

// single-pass exclusive scan (decoupled lookback); g_flag zero at entry
__global__ void scan_k(int N) {
    __shared__ int wsum[16];
    __shared__ int s_off;
    int tid = threadIdx.x, b = blockIdx.x;
    int lane = tid & 31, wid = tid >> 5;
    int i = b * SCAN_B + tid;
    int v = (i < N) ? g_deg[i] : 0;

    int x = v;
#pragma unroll
    for (int o = 1; o < 32; o <<= 1) {
        int t = __shfl_up_sync(0xffffffffu, x, o);
        if (lane >= o) x += t;
    }
    if (lane == 31) wsum[wid] = x;
    __syncthreads();
    if (wid == 0 && lane < 16) {
        int y = wsum[lane];
#pragma unroll
        for (int o = 1; o < 16; o <<= 1) {
            int t = __shfl_up_sync(0x0000ffffu, y, o);
            if (lane >= o) y += t;
        }
        wsum[lane] = y;
    }
    __syncthreads();
    int incl  = x + (wid > 0 ? wsum[wid - 1] : 0);
    int total = wsum[15];

    if (tid == 0) {
        if (b == 0) {
            g_incl[0] = total;
            __threadfence();
            g_flag[0] = 2;
            s_off = 0;
        } else {
            g_aggr[b] = total;
            __threadfence();
            g_flag[b] = 1;
            int run = 0;
            for (int p = b - 1; p >= 0; p--) {
                int f;
                do { f = g_flag[p]; } while (f == 0);
                if (f == 2) { run += g_incl[p]; break; }
                run += g_aggr[p];
            }
            s_off = run;
            g_incl[b] = run + total;
            __threadfence();
            g_flag[b] = 2;
        }
    }
    __syncthreads();
    if (i < N) g_rowptr[i] = s_off + incl - v;     // exclusive
}

__global__ void scatter_k(const int* __restrict__ ei, int E) {
    int i4 = blockIdx.x * blockDim.x + threadIdx.x;
    int base = i4 * 4;
    if (base + 3 < E) {
        int4 s = *(const int4*)(ei + base);
        int4 d = *(const int4*)(ei + E + base);
        g_csrc[atomicAdd(&g_rowptr[d.x], 1)] = s.x;
        g_csrc[atomicAdd(&g_rowptr[d.y], 1)] = s.y;
        g_csrc[atomicAdd(&g_rowptr[d.z], 1)] = s.z;
        g_csrc[atomicAdd(&g_rowptr[d.w], 1)] = s.w;
    } else {
        for (int i = base; i < E; i++)
            g_csrc[atomicAdd(&g_rowptr[ei[E + i]], 1)] = ei[i];
    }
}

// restore zeroed-state invariant for the next call (runs LAST)
__global__ void cleanup(int N) {
    int i = blockIdx.x * blockDim.x + threadIdx.x;
    if (i < N) g_deg[i] = 0;
    if (i < MAXBLK) g_flag[i] = 0;
}

// ================= K1: register-tiled GEMM + attention scores =================
// 128x64 output tile, 128 threads, 8x8 per thread, packed f32x2 accumulators
// (row pairs). As swizzled [k][r] (XOR on 16B groups, conflict-light transpose
// fill + broadcast a-frag loads); Bs [k][c] zero-padded beyond Do.
// Per k: 4 LDS.64 (a) + 2 LDS.128 (b) + 8 packs + 32 FFMA2 (=64 FMA).
template <int Do, bool FROMG>
__global__ void __launch_bounds__(128) gemm_attn(
        const float* __restrict__ xin, const float* __restrict__ W,
        const float* __restrict__ a_s, const float* __restrict__ a_d, int N) {
    const int Din = 64;
    __shared__ float As[Din * 128];    // 32KB, swizzled
    __shared__ float Bs[Din * 64];     // 16KB

    int t  = threadIdx.x;              // 0..127
    int tx = t & 7;                    // col group (8 cols each)
    int ty = t >> 3;                   // row group (8 rows each)
    int rowbase = blockIdx.x * 128;

    const float* src = FROMG ? g_x : xin;

    // fill As (transpose x into [k][r] with group swizzle g ^= k&31)
    {
        int kg = (t & 15) * 4;         // base k of this thread's float4
        int r0 = t >> 4;               // 0..7
#pragma unroll
        for (int q = 0; q < 16; q++) {
            int r = r0 + q * 8;
            int row = rowbase + r;
            float4 x4 = (row < N) ? *(const float4*)(src + (size_t)row * Din + kg)
                                  : make_float4(0.f, 0.f, 0.f, 0.f);
            int rg = r >> 2, rl = r & 3;
            As[(kg + 0) * 128 + ((rg ^ ((kg + 0) & 31)) << 2) + rl] = x4.x;
            As[(kg + 1) * 128 + ((rg ^ ((kg + 1) & 31)) << 2) + rl] = x4.y;
            As[(kg + 2) * 128 + ((rg ^ ((kg + 2) & 31)) << 2) + rl] = x4.z;
            As[(kg + 3) * 128 + ((rg ^ ((kg + 3) & 31)) << 2) + rl] = x4.w;
        }
    }
    // fill Bs
    {
        int c4 = (t & 15) * 4;
        int k0 = t >> 4;
#pragma unroll
        for (int q = 0; q < 8; q++) {
            int k = k0 + q * 8;
            float4 w4 = (c4 < Do) ? *(const float4*)(W + (size_t)k * Do + c4)
                                  : make_float4(0.f, 0.f, 0.f, 0.f);
            *(float4*)&Bs[k * 64 + c4] = w4;
        }
    }
    __syncthreads();

    ull acc2[4][8];                    // [row-pair][col], packed {row2i, row2i+1}
#pragma unroll
    for (int i = 0; i < 4; i++)
#pragma unroll
        for (int c = 0; c < 8; c++) acc2[i][c] = 0ull;

#pragma unroll 4
    for (int k = 0; k < Din; k++) {
        int sw = k & 31;
        const float* arow = &As[k * 128];
        int g0 = ((ty * 2) ^ sw) << 2;       // float index of rows ty*8..+3
        int g1 = ((ty * 2 + 1) ^ sw) << 2;   // rows ty*8+4..+7
        ull a01 = *(const ull*)(arow + g0);
        ull a23 = *(const ull*)(arow + g0 + 2);
        ull a45 = *(const ull*)(arow + g1);
        ull a67 = *(const ull*)(arow + g1 + 2);
        float4 b0 = *(const float4*)&Bs[k * 64 + tx * 8];
        float4 b1 = *(const float4*)&Bs[k * 64 + tx * 8 + 4];
        ull bp0, bp1, bp2, bp3, bp4, bp5, bp6, bp7;
        PK2(bp0, b0.x, b0.x); PK2(bp1, b0.y, b0.y);
        PK2(bp2, b0.z, b0.z); PK2(bp3, b0.w, b0.w);
        PK2(bp4, b1.x, b1.x); PK2(bp5, b1.y, b1.y);
        PK2(bp6, b1.z, b1.z); PK2(bp7, b1.w, b1.w);
        FMA2(acc2[0][0], a01, bp0, acc2[0][0]); FMA2(acc2[0][1], a01, bp1, acc2[0][1]);
        FMA2(acc2[0][2], a01, bp2, acc2[0][2]); FMA2(acc2[0][3], a01, bp3, acc2[0][3]);
        FMA2(acc2[0][4], a01, bp4, acc2[0][4]); FMA2(acc2[0][5], a01, bp5, acc2[0][5]);
        FMA2(acc2[0][6], a01, bp6, acc2[0][6]); FMA2(acc2[0][7], a01, bp7, acc2[0][7]);
        FMA2(acc2[1][0], a23, bp0, acc2[1][0]); FMA2(acc2[1][1], a23, bp1, acc2[1][1]);
        FMA2(acc2[1][2], a23, bp2, acc2[1][2]); FMA2(acc2[1][3], a23, bp3, acc2[1][3]);
        FMA2(acc2[1][4], a23, bp4, acc2[1][4]); FMA2(acc2[1][5], a23, bp5, acc2[1][5]);
        FMA2(acc2[1][6], a23, bp6, acc2[1][6]); FMA2(acc2[1][7], a23, bp7, acc2[1][7]);
        FMA2(acc2[2][0], a45, bp0, acc2[2][0]); FMA2(acc2[2][1], a45, bp1, acc2[2][1]);
        FMA2(acc2[2][2], a45, bp2, acc2[2][2]); FMA2(acc2[2][3], a45, bp3, acc2[2][3]);
        FMA2(acc2[2][4], a45, bp4, acc2[2][4]); FMA2(acc2[2][5], a45, bp5, acc2[2][5]);
        FMA2(acc2[2][6], a45, bp6, acc2[2][6]); FMA2(acc2[2][7], a45, bp7, acc2[2][7]);
        FMA2(acc2[3][0], a67, bp0, acc2[3][0]); FMA2(acc2[3][1], a67, bp1, acc2[3][1]);
        FMA2(acc2[3][2], a67, bp2, acc2[3][2]); FMA2(acc2[3][3], a67, bp3, acc2[3][3]);
        FMA2(acc2[3][4], a67, bp4, acc2[3][4]); FMA2(acc2[3][5], a67, bp5, acc2[3][5]);
        FMA2(acc2[3][6], a67, bp6, acc2[3][6]); FMA2(acc2[3][7], a67, bp7, acc2[3][7]);
    }

    // unpack to scalar 8x8
    float acc[8][8];
#pragma unroll
    for (int i = 0; i < 4; i++)
#pragma unroll
        for (int c = 0; c < 8; c++)
            UPK2(acc[2 * i][c], acc[2 * i + 1][c], acc2[i][c]);

    int c8 = tx * 8;
    float av8[8], dv8[8];
#pragma unroll
    for (int c = 0; c < 8; c++) {
        av8[c] = (c8 + c < Do) ? a_s[c8 + c] : 0.f;
        dv8[c] = (c8 + c < Do) ? a_d[c8 + c] : 0.f;
    }

#pragma unroll
    for (int i = 0; i < 8; i++) {
        int row = rowbase + ty * 8 + i;
        float ps = 0.f, pd = 0.f;
#pragma unroll
        for (int c = 0; c < 8; c++) { ps += acc[i][c] * av8[c]; pd += acc[i][c] * dv8[c]; }
#pragma unroll
        for (int o = 4; o > 0; o >>= 1) {
            ps += __shfl_xor_sync(0xffffffffu, ps, o);
            pd += __shfl_xor_sync(0xffffffffu, pd, o);
        }
        if (row < N) {
            if (c8 < Do)
                *(float4*)(g_h + (size_t)row * Do + c8) =
                    make_float4(acc[i][0], acc[i][1], acc[i][2], acc[i][3]);
            if (c8 + 4 < Do)
                *(float4*)(g_h + (size_t)row * Do + c8 + 4) =
                    make_float4(acc[i][4], acc[i][5], acc[i][6], acc[i][7]);
            if (tx == 0) { g_as[row] = ps; g_ad[row] = pd; }
        }
    }
}

// ================= K2: softmax + aggregate (warp per node, float2 lanes) =====
// Shift by self-score (softmax shift-invariant; scores O(10), fp32-safe).
// MODE 0: relu(acc/den + b) -> g_x (Do=64, GOUT=true); MODE 1: log_softmax -> out.
template <int Do, int MODE, bool GOUT>
__global__ void agg(const float* __restrict__ b, float* __restrict__ out_arg, int N) {
    const unsigned FULL = 0xffffffffu;
    float* out = GOUT ? g_x : out_arg;
    int w    = (blockIdx.x * blockDim.x + threadIdx.x) >> 5;
    int lane = threadIdx.x & 31;
    if (w >= N) return;
    const int n = w;

    int end   = g_rowptr[n];
    int start = end - g_deg[n];
    float ad_n  = g_ad[n];
    float eself = lrelu(g_as[n] + ad_n);

    const int HL = Do / 2;
    bool act = (lane < HL);
    float2 acc = act ? *(const float2*)(g_h + (size_t)n * Do + 2 * lane)
                     : make_float2(0.f, 0.f);            // self contribution (ex=1)
    float den_p = (lane == 0) ? 1.f : 0.f;

    for (int base = start; base < end; base += 32) {
        int i = base + lane;
        int   s = 0;
        float ex = 0.f;
        if (i < end) {
            s  = g_csrc[i];
            ex = __expf(lrelu(g_as[s] + ad_n) - eself);
        }
        den_p += ex;

        int cnt = min(32, end - base);
        int j = 0;
        for (; j + 4 <= cnt; j += 4) {
            int   s0 = __shfl_sync(FULL, s, j),     s1 = __shfl_sync(FULL, s, j + 1);
            int   s2 = __shfl_sync(FULL, s, j + 2), s3 = __shfl_sync(FULL, s, j + 3);
            float e0 = __shfl_sync(FULL, ex, j),     e1 = __shfl_sync(FULL, ex, j + 1);
            float e2 = __shfl_sync(FULL, ex, j + 2), e3 = __shfl_sync(FULL, ex, j + 3);
            if (act) {
                float2 h0 = *(const float2*)(g_h + (size_t)s0 * Do + 2 * lane);
                float2 h1 = *(const float2*)(g_h + (size_t)s1 * Do + 2 * lane);
                float2 h2 = *(const float2*)(g_h + (size_t)s2 * Do + 2 * lane);
                float2 h3 = *(const float2*)(g_h + (size_t)s3 * Do + 2 * lane);
                acc.x += e0 * h0.x; acc.y += e0 * h0.y;
                acc.x += e1 * h1.x; acc.y += e1 * h1.y;
                acc.x += e2 * h2.x; acc.y += e2 * h2.y;
                acc.x += e3 * h3.x; acc.y += e3 * h3.y;
            }
        }
        for (; j < cnt; j++) {
            int   sj = __shfl_sync(FULL, s, j);
            float ej = __shfl_sync(FULL, ex, j);
            if (act) {
                float2 hj = *(const float2*)(g_h + (size_t)sj * Do + 2 * lane);
                acc.x += ej * hj.x; acc.y += ej * hj.y;
            }
        }
    }
#pragma unroll
    for (int o = 16; o > 0; o >>= 1)
        den_p += __shfl_xor_sync(FULL, den_p, o);
    float inv = 1.f / den_p;

    if (MODE == 0) {
        float2 bv = *(const float2*)(b + 2 * lane);
        float2 o2;
        o2.x = fmaxf(acc.x * inv + bv.x, 0.f);
        o2.y = fmaxf(acc.y * inv + bv.y, 0.f);
        *(float2*)(out + (size_t)n * 64 + 2 * lane) = o2;
    } else {
        float v0 = act ? (acc.x * inv + b[2 * lane])     : -INFINITY;
        float v1 = act ? (acc.y * inv + b[2 * lane + 1]) : -INFINITY;
        float mx = fmaxf(v0, v1);
#pragma unroll
        for (int o = 16; o > 0; o >>= 1)
            mx = fmaxf(mx, __shfl_xor_sync(FULL, mx, o));
        float sum = act ? (expf(v0 - mx) + expf(v1 - mx)) : 0.f;
#pragma unroll
        for (int o = 16; o > 0; o >>= 1)
            sum += __shfl_xor_sync(FULL, sum, o);
        float ls = mx + logf(sum);
        if (act) {
            out[(size_t)n * 40 + 2 * lane]     = v0 - ls;
            out[(size_t)n * 40 + 2 * lane + 1] = v1 - ls;
        }
    }
}

extern "C" void kernel_launch(void* const* d_in, const int* in_sizes, int n_in,
                              void* d_out, int out_size) {
    const int N = in_sizes[0] / 64;
    const int E = in_sizes[1] / 2;
    const float* x  = (const float*)d_in[0];
    const int*   ei = (const int*)d_in[1];     // int32 (JAX downcasts int64)

    const int TB = 256;
    int nblk  = (N + TB - 1) / TB;
    int e4blk = ((E + 3) / 4 + TB - 1) / TB;
    int sblk  = (N + SCAN_B - 1) / SCAN_B;
    int gemm_grid = (N + 127) / 128;
    int agg_grid  = (N + 7) / 8;

    // ---- CSR build ----
    hist_k<<<e4blk, TB>>>(ei, E);
    scan_k<<<sblk, SCAN_B>>>(N);
    scatter_k<<<e4blk, TB>>>(ei, E);

    // ---------- layer 0 ----------
    gemm_attn<64, false><<<gemm_grid, 128>>>(x, (const float*)d_in[2],
                                             (const float*)d_in[3], (const float*)d_in[4], N);
    agg<64, 0, true><<<agg_grid, TB>>>((const float*)d_in[5], nullptr, N);

    // ---------- layer 1 ----------
    gemm_attn<64, true><<<gemm_grid, 128>>>(nullptr, (const float*)d_in[6],
                                            (const float*)d_in[7], (const float*)d_in[8], N);
    agg<64, 0, true><<<agg_grid, TB>>>((const float*)d_in[9], nullptr, N);

    // ---------- layer 2 ----------
    gemm_attn<40, true><<<gemm_grid, 128>>>(nullptr, (const float*)d_in[10],
                                            (const float*)d_in[11], (const float*)d_in[12], N);
    agg<40, 1, false><<<agg_grid, TB>>>((const float*)d_in[13], (float*)d_out, N);

    // ---- restore zeroed-state invariant for next call ----
    cleanup<<<nblk, TB>>>(N);
}